// round 1
// baseline (speedup 1.0000x reference)
#include <cuda_runtime.h>

// Problem constants
#define N_TOK 4096
#define DIM   512
#define ODIM  512
#define NEXP  8
#define TOPK  2

// GEMM tiling
#define BM 128
#define BN 128
#define BK 8
#define MAXROWS (N_TOK*TOPK + NEXP*BM)   // 8192 + 1024 = 9216 (padded upper bound)
#define MTILES  (MAXROWS/BM)             // 72

// ---------------- device scratch (no allocations allowed) ----------------
__device__ int   g_counts[NEXP];
__device__ int   g_offsets[NEXP + 1];
__device__ int   g_cursor[NEXP];
__device__ int   g_row_token[MAXROWS];       // grouped row -> token id (-1 = padding)
__device__ int   g_top_e[N_TOK * TOPK];      // per token: top-2 expert ids (slot order)
__device__ int   g_tok_rows[N_TOK * TOPK];   // per token: grouped row index per slot
__device__ float g_tok_w[N_TOK * TOPK];      // per token: slot combine weights
__device__ float g_h1[(size_t)MAXROWS * ODIM];  // layer1 out, reused as layer3 out (y)
__device__ float g_h2[(size_t)MAXROWS * ODIM];  // layer2 out

// ---------------- init ----------------
__global__ void init_kernel() {
    int i = blockIdx.x * blockDim.x + threadIdx.x;
    if (i < NEXP) g_counts[i] = 0;
    if (i < MAXROWS) g_row_token[i] = -1;
}

// ---------------- gating: one warp per token ----------------
__global__ void gate_kernel(const float* __restrict__ x,
                            const float* __restrict__ gw,
                            const float* __restrict__ gb) {
    int warp = (blockIdx.x * blockDim.x + threadIdx.x) >> 5;
    int lane = threadIdx.x & 31;
    if (warp >= N_TOK) return;
    const float* xr = x + (size_t)warp * DIM;

    float acc[NEXP];
#pragma unroll
    for (int e = 0; e < NEXP; ++e) acc[e] = 0.f;

    for (int i = lane; i < DIM; i += 32) {
        float xv = xr[i];
        const float4* g4 = (const float4*)(gw + (size_t)i * NEXP);
        float4 a = g4[0], b = g4[1];
        acc[0] += xv * a.x; acc[1] += xv * a.y; acc[2] += xv * a.z; acc[3] += xv * a.w;
        acc[4] += xv * b.x; acc[5] += xv * b.y; acc[6] += xv * b.z; acc[7] += xv * b.w;
    }
#pragma unroll
    for (int e = 0; e < NEXP; ++e) {
#pragma unroll
        for (int off = 16; off; off >>= 1)
            acc[e] += __shfl_xor_sync(0xffffffffu, acc[e], off);
    }

    if (lane == 0) {
        float lg[NEXP];
        float mx = -1e30f;
#pragma unroll
        for (int e = 0; e < NEXP; ++e) {
            lg[e] = acc[e] + gb[e];
            mx = fmaxf(mx, lg[e]);
        }
        float p[NEXP], s = 0.f;
#pragma unroll
        for (int e = 0; e < NEXP; ++e) { p[e] = expf(lg[e] - mx); s += p[e]; }
        float inv = 1.0f / s;

        // top-2 on logits (same order as softmax probs); tie -> lowest index
        int i0 = 0;
#pragma unroll
        for (int e = 1; e < NEXP; ++e) if (lg[e] > lg[i0]) i0 = e;
        int i1 = -1;
#pragma unroll
        for (int e = 0; e < NEXP; ++e)
            if (e != i0 && (i1 < 0 || lg[e] > lg[i1])) i1 = e;

        // Faithful quirk: slot j combine weight is probs[n, j] (experts 0/1 probs)
        float w0 = p[0] * inv;
        float w1 = p[1] * inv;

        g_top_e[warp * 2 + 0] = i0;
        g_top_e[warp * 2 + 1] = i1;
        g_tok_w[warp * 2 + 0] = w0;
        g_tok_w[warp * 2 + 1] = w1;
        atomicAdd(&g_counts[i0], 1);
        atomicAdd(&g_counts[i1], 1);
    }
}

// ---------------- offsets (padded to BM per expert) ----------------
__global__ void offsets_kernel() {
    int t = threadIdx.x;
    if (t == 0) {
        int off = 0;
#pragma unroll
        for (int e = 0; e < NEXP; ++e) {
            g_offsets[e] = off;
            off += ((g_counts[e] + BM - 1) / BM) * BM;
        }
        g_offsets[NEXP] = off;
    }
    if (t < NEXP) g_cursor[t] = 0;
}

// ---------------- scatter: build grouped row list + inverse map ----------------
__global__ void scatter_kernel() {
    int i = blockIdx.x * blockDim.x + threadIdx.x;
    if (i >= N_TOK * TOPK) return;
    int e = g_top_e[i];
    int pos = atomicAdd(&g_cursor[e], 1);
    int r = g_offsets[e] + pos;
    g_row_token[r] = i >> 1;
    g_tok_rows[i] = r;
}

// ---------------- grouped GEMM: C = relu(A @ W[e] + bias[e]) ----------------
// LAYER 0: A = x (gathered via g_row_token), C = g_h1
// LAYER 1: A = g_h1,                         C = g_h2
// LAYER 2: A = g_h2,                         C = g_h1 (y)
template <int LAYER>
__global__ void __launch_bounds__(256, 2)
moe_gemm(const float* __restrict__ xin,
         const float* __restrict__ W,
         const float* __restrict__ Bias) {
    constexpr bool GATHER = (LAYER == 0);
    const float* A = GATHER ? xin : (LAYER == 1 ? g_h1 : g_h2);
    float* C = (LAYER == 1) ? g_h2 : g_h1;

    int mbase = blockIdx.y * BM;
    if (mbase >= g_offsets[NEXP]) return;   // beyond last expert segment

    int e = 0;
    while (e < NEXP - 1 && mbase >= g_offsets[e + 1]) e++;

    const float* Wb = W + (size_t)e * DIM * ODIM;
    int nbase = blockIdx.x * BN;

    __shared__ float As[BK][BM];
    __shared__ float Bs[BK][BN];
    __shared__ int rtok[BM];

    int tid = threadIdx.x;
    if (GATHER) {
        if (tid < BM) rtok[tid] = g_row_token[mbase + tid];
    }
    __syncthreads();

    int arow = tid >> 1;          // 0..127
    int acol = (tid & 1) * 4;     // 0 or 4 (k offset within BK)
    int brow = tid >> 5;          // 0..7
    int bcol = (tid & 31) * 4;    // 0..124
    int tx = tid & 15, ty = tid >> 4;

    const float* Aptr;
    bool avalid = true;
    if (GATHER) {
        int rt = rtok[arow];
        avalid = (rt >= 0);
        Aptr = xin + (avalid ? (size_t)rt * DIM : 0) + acol;
    } else {
        Aptr = A + (size_t)(mbase + arow) * DIM + acol;
    }
    const float* Bptr = Wb + (size_t)brow * ODIM + nbase + bcol;

    float accv[8][8];
#pragma unroll
    for (int i = 0; i < 8; ++i)
#pragma unroll
        for (int j = 0; j < 8; ++j) accv[i][j] = 0.f;

    for (int k0 = 0; k0 < DIM; k0 += BK) {
        float4 av = avalid ? *(const float4*)(Aptr + k0)
                           : make_float4(0.f, 0.f, 0.f, 0.f);
        float4 bv = *(const float4*)(Bptr + (size_t)k0 * ODIM);
        __syncthreads();   // previous compute done before overwriting smem
        As[acol + 0][arow] = av.x;
        As[acol + 1][arow] = av.y;
        As[acol + 2][arow] = av.z;
        As[acol + 3][arow] = av.w;
        *(float4*)&Bs[brow][bcol] = bv;
        __syncthreads();

#pragma unroll
        for (int k = 0; k < BK; ++k) {
            float ra[8], rb[8];
            float4 t0 = *(const float4*)&As[k][ty * 8];
            float4 t1 = *(const float4*)&As[k][ty * 8 + 4];
            ra[0] = t0.x; ra[1] = t0.y; ra[2] = t0.z; ra[3] = t0.w;
            ra[4] = t1.x; ra[5] = t1.y; ra[6] = t1.z; ra[7] = t1.w;
            float4 u0 = *(const float4*)&Bs[k][tx * 8];
            float4 u1 = *(const float4*)&Bs[k][tx * 8 + 4];
            rb[0] = u0.x; rb[1] = u0.y; rb[2] = u0.z; rb[3] = u0.w;
            rb[4] = u1.x; rb[5] = u1.y; rb[6] = u1.z; rb[7] = u1.w;
#pragma unroll
            for (int i = 0; i < 8; ++i)
#pragma unroll
                for (int j = 0; j < 8; ++j)
                    accv[i][j] = fmaf(ra[i], rb[j], accv[i][j]);
        }
    }

    // epilogue: bias + relu
    float4 bv0 = *(const float4*)&Bias[(size_t)e * ODIM + nbase + tx * 8];
    float4 bv1 = *(const float4*)&Bias[(size_t)e * ODIM + nbase + tx * 8 + 4];
    float bb[8] = {bv0.x, bv0.y, bv0.z, bv0.w, bv1.x, bv1.y, bv1.z, bv1.w};

#pragma unroll
    for (int i = 0; i < 8; ++i) {
        int m = mbase + ty * 8 + i;
        float4 o0, o1;
        o0.x = fmaxf(accv[i][0] + bb[0], 0.f);
        o0.y = fmaxf(accv[i][1] + bb[1], 0.f);
        o0.z = fmaxf(accv[i][2] + bb[2], 0.f);
        o0.w = fmaxf(accv[i][3] + bb[3], 0.f);
        o1.x = fmaxf(accv[i][4] + bb[4], 0.f);
        o1.y = fmaxf(accv[i][5] + bb[5], 0.f);
        o1.z = fmaxf(accv[i][6] + bb[6], 0.f);
        o1.w = fmaxf(accv[i][7] + bb[7], 0.f);
        float* crow = C + (size_t)m * ODIM + nbase + tx * 8;
        *(float4*)(crow + 0) = o0;
        *(float4*)(crow + 4) = o1;
    }
}

// ---------------- combine: out[tok] = w0*y[r0] + w1*y[r1] (fixed order) ----------------
__global__ void combine_kernel(float* __restrict__ out) {
    int tok = blockIdx.x;
    int r0 = g_tok_rows[tok * 2 + 0];
    int r1 = g_tok_rows[tok * 2 + 1];
    float w0 = g_tok_w[tok * 2 + 0];
    float w1 = g_tok_w[tok * 2 + 1];
    const float4* y0 = (const float4*)(g_h1 + (size_t)r0 * ODIM);
    const float4* y1 = (const float4*)(g_h1 + (size_t)r1 * ODIM);
    float4* o = (float4*)(out + (size_t)tok * ODIM);
    for (int c = threadIdx.x; c < ODIM / 4; c += blockDim.x) {
        float4 a = y0[c], b = y1[c];
        float4 r;
        r.x = w0 * a.x + w1 * b.x;
        r.y = w0 * a.y + w1 * b.y;
        r.z = w0 * a.z + w1 * b.z;
        r.w = w0 * a.w + w1 * b.w;
        o[c] = r;
    }
}

// ---------------- launch ----------------
extern "C" void kernel_launch(void* const* d_in, const int* in_sizes, int n_in,
                              void* d_out, int out_size) {
    const float* x  = (const float*)d_in[0];
    const float* gw = (const float*)d_in[1];
    const float* gb = (const float*)d_in[2];
    const float* w1 = (const float*)d_in[3];
    const float* b1 = (const float*)d_in[4];
    const float* w2 = (const float*)d_in[5];
    const float* b2 = (const float*)d_in[6];
    const float* w3 = (const float*)d_in[7];
    const float* b3 = (const float*)d_in[8];
    float* out = (float*)d_out;

    init_kernel<<<(MAXROWS + 255) / 256, 256>>>();
    gate_kernel<<<N_TOK / 8, 256>>>(x, gw, gb);
    offsets_kernel<<<1, 32>>>();
    scatter_kernel<<<(N_TOK * TOPK + 255) / 256, 256>>>();

    dim3 grid(ODIM / BN, MTILES);
    moe_gemm<0><<<grid, 256>>>(x, w1, b1);
    moe_gemm<1><<<grid, 256>>>(x, w2, b2);
    moe_gemm<2><<<grid, 256>>>(x, w3, b3);

    combine_kernel<<<N_TOK, 128>>>(out);
}

// round 3
// speedup vs baseline: 1.0247x; 1.0247x over previous
#include <cuda_runtime.h>

// Problem constants
#define N_TOK 4096
#define DIM   512
#define ODIM  512
#define NEXP  8
#define TOPK  2

// GEMM tiling
#define BM 128
#define BN 128
#define BK 8
#define MAXROWS (N_TOK*TOPK + NEXP*BM)   // 9216 (padded upper bound)
#define MTILES  (MAXROWS/BM)             // 72

typedef unsigned long long u64;

// packed f32x2 helpers (Blackwell-only FFMA2 path, exact fp32 semantics)
__device__ __forceinline__ u64 pack2(float lo, float hi) {
    u64 r; asm("mov.b64 %0, {%1, %2};" : "=l"(r) : "f"(lo), "f"(hi)); return r;
}
__device__ __forceinline__ void unpack2(u64 v, float& lo, float& hi) {
    asm("mov.b64 {%0, %1}, %2;" : "=f"(lo), "=f"(hi) : "l"(v));
}
__device__ __forceinline__ void ffma2(u64& d, u64 a, u64 b) {
    asm("fma.rn.f32x2 %0, %1, %2, %3;" : "=l"(d) : "l"(a), "l"(b), "l"(d));
}

// ---------------- device scratch (no allocations allowed) ----------------
__device__ int   g_counts[NEXP];
__device__ int   g_offsets[NEXP + 1];
__device__ int   g_cursor[NEXP];
__device__ int   g_row_token[MAXROWS];       // grouped row -> token id (-1 = padding)
__device__ int   g_top_e[N_TOK * TOPK];      // per token: top-2 expert ids (slot order)
__device__ int   g_tok_rows[N_TOK * TOPK];   // per token: grouped row index per slot
__device__ float g_tok_w[N_TOK * TOPK];      // per token: slot combine weights
__device__ float g_h1[(size_t)MAXROWS * ODIM];  // layer1 out, reused as layer3 out (y)
__device__ float g_h2[(size_t)MAXROWS * ODIM];  // layer2 out

// ---------------- init ----------------
__global__ void init_kernel() {
    int i = blockIdx.x * blockDim.x + threadIdx.x;
    if (i < NEXP) g_counts[i] = 0;
    if (i < MAXROWS) g_row_token[i] = -1;
}

// ---------------- gating: one warp per token ----------------
__global__ void gate_kernel(const float* __restrict__ x,
                            const float* __restrict__ gw,
                            const float* __restrict__ gb) {
    int warp = (blockIdx.x * blockDim.x + threadIdx.x) >> 5;
    int lane = threadIdx.x & 31;
    if (warp >= N_TOK) return;
    const float* xr = x + (size_t)warp * DIM;

    float acc[NEXP];
#pragma unroll
    for (int e = 0; e < NEXP; ++e) acc[e] = 0.f;

    for (int i = lane; i < DIM; i += 32) {
        float xv = xr[i];
        const float4* g4 = (const float4*)(gw + (size_t)i * NEXP);
        float4 a = g4[0], b = g4[1];
        acc[0] += xv * a.x; acc[1] += xv * a.y; acc[2] += xv * a.z; acc[3] += xv * a.w;
        acc[4] += xv * b.x; acc[5] += xv * b.y; acc[6] += xv * b.z; acc[7] += xv * b.w;
    }
#pragma unroll
    for (int e = 0; e < NEXP; ++e) {
#pragma unroll
        for (int off = 16; off; off >>= 1)
            acc[e] += __shfl_xor_sync(0xffffffffu, acc[e], off);
    }

    if (lane == 0) {
        float lg[NEXP];
        float mx = -1e30f;
#pragma unroll
        for (int e = 0; e < NEXP; ++e) {
            lg[e] = acc[e] + gb[e];
            mx = fmaxf(mx, lg[e]);
        }
        float p[NEXP], s = 0.f;
#pragma unroll
        for (int e = 0; e < NEXP; ++e) { p[e] = expf(lg[e] - mx); s += p[e]; }
        float inv = 1.0f / s;

        // top-2 on logits (same order as softmax probs); tie -> lowest index
        int i0 = 0;
#pragma unroll
        for (int e = 1; e < NEXP; ++e) if (lg[e] > lg[i0]) i0 = e;
        int i1 = -1;
#pragma unroll
        for (int e = 0; e < NEXP; ++e)
            if (e != i0 && (i1 < 0 || lg[e] > lg[i1])) i1 = e;

        // Faithful quirk: slot j combine weight is probs[n, j] (experts 0/1 probs)
        float w0 = p[0] * inv;
        float w1 = p[1] * inv;

        g_top_e[warp * 2 + 0] = i0;
        g_top_e[warp * 2 + 1] = i1;
        g_tok_w[warp * 2 + 0] = w0;
        g_tok_w[warp * 2 + 1] = w1;
        atomicAdd(&g_counts[i0], 1);
        atomicAdd(&g_counts[i1], 1);
    }
}

// ---------------- offsets (padded to BM per expert) ----------------
__global__ void offsets_kernel() {
    int t = threadIdx.x;
    if (t == 0) {
        int off = 0;
#pragma unroll
        for (int e = 0; e < NEXP; ++e) {
            g_offsets[e] = off;
            off += ((g_counts[e] + BM - 1) / BM) * BM;
        }
        g_offsets[NEXP] = off;
    }
    if (t < NEXP) g_cursor[t] = 0;
}

// ---------------- scatter: build grouped row list + inverse map ----------------
__global__ void scatter_kernel() {
    int i = blockIdx.x * blockDim.x + threadIdx.x;
    if (i >= N_TOK * TOPK) return;
    int e = g_top_e[i];
    int pos = atomicAdd(&g_cursor[e], 1);
    int r = g_offsets[e] + pos;
    g_row_token[r] = i >> 1;
    g_tok_rows[i] = r;
}

// ---------------- grouped GEMM: C = relu(A @ W[e] + bias[e]) ----------------
// LAYER 0: A = x (gathered via g_row_token), C = g_h1
// LAYER 1: A = g_h1,                         C = g_h2
// LAYER 2: A = g_h2,                         C = g_h1 (y)
template <int LAYER>
__global__ void __launch_bounds__(256, 2)
moe_gemm(const float* __restrict__ xin,
         const float* __restrict__ W,
         const float* __restrict__ Bias) {
    constexpr bool GATHER = (LAYER == 0);
    const float* A = GATHER ? xin : (LAYER == 1 ? g_h1 : g_h2);
    float* C = (LAYER == 1) ? g_h2 : g_h1;

    int mbase = blockIdx.y * BM;
    if (mbase >= g_offsets[NEXP]) return;   // beyond last expert segment

    int e = 0;
    while (e < NEXP - 1 && mbase >= g_offsets[e + 1]) e++;

    const float* Wb = W + (size_t)e * DIM * ODIM;
    int nbase = blockIdx.x * BN;

    __shared__ float As[BK][BM];
    __shared__ float Bs[BK][BN];
    __shared__ int rtok[BM];

    int tid = threadIdx.x;
    if (GATHER) {
        if (tid < BM) rtok[tid] = g_row_token[mbase + tid];
    }
    __syncthreads();

    int arow = tid >> 1;          // 0..127
    int acol = (tid & 1) * 4;     // 0 or 4 (k offset within BK)
    int brow = tid >> 5;          // 0..7
    int bcol = (tid & 31) * 4;    // 0..124
    int tx = tid & 15, ty = tid >> 4;

    const float* Aptr;
    bool avalid = true;
    if (GATHER) {
        int rt = rtok[arow];
        avalid = (rt >= 0);
        Aptr = xin + (avalid ? (size_t)rt * DIM : 0) + acol;
    } else {
        Aptr = A + (size_t)(mbase + arow) * DIM + acol;
    }
    const float* Bptr = Wb + (size_t)brow * ODIM + nbase + bcol;

    // 8x8 micro-tile as 8x4 packed f32x2 accumulators
    u64 acc[8][4];
#pragma unroll
    for (int i = 0; i < 8; ++i)
#pragma unroll
        for (int j = 0; j < 4; ++j) acc[i][j] = 0ull;

    for (int k0 = 0; k0 < DIM; k0 += BK) {
        float4 av = avalid ? *(const float4*)(Aptr + k0)
                           : make_float4(0.f, 0.f, 0.f, 0.f);
        float4 bv = *(const float4*)(Bptr + (size_t)k0 * ODIM);
        __syncthreads();   // previous compute done before overwriting smem
        As[acol + 0][arow] = av.x;
        As[acol + 1][arow] = av.y;
        As[acol + 2][arow] = av.z;
        As[acol + 3][arow] = av.w;
        *(float4*)&Bs[brow][bcol] = bv;
        __syncthreads();

#pragma unroll
        for (int k = 0; k < BK; ++k) {
            // A fragment: 8 values broadcast into packed pairs (alu pipe)
            float4 t0 = *(const float4*)&As[k][ty * 8];
            float4 t1 = *(const float4*)&As[k][ty * 8 + 4];
            u64 ra2[8];
            ra2[0] = pack2(t0.x, t0.x); ra2[1] = pack2(t0.y, t0.y);
            ra2[2] = pack2(t0.z, t0.z); ra2[3] = pack2(t0.w, t0.w);
            ra2[4] = pack2(t1.x, t1.x); ra2[5] = pack2(t1.y, t1.y);
            ra2[6] = pack2(t1.z, t1.z); ra2[7] = pack2(t1.w, t1.w);
            // B fragment: pairs of adjacent columns, aliased from LDS.128 regs
            float4 u0 = *(const float4*)&Bs[k][tx * 8];
            float4 u1 = *(const float4*)&Bs[k][tx * 8 + 4];
            u64 rb2[4];
            rb2[0] = pack2(u0.x, u0.y); rb2[1] = pack2(u0.z, u0.w);
            rb2[2] = pack2(u1.x, u1.y); rb2[3] = pack2(u1.z, u1.w);
#pragma unroll
            for (int i = 0; i < 8; ++i) {
#pragma unroll
                for (int j = 0; j < 4; ++j)
                    ffma2(acc[i][j], ra2[i], rb2[j]);
            }
        }
    }

    // epilogue: bias + relu
    float4 bv0 = *(const float4*)&Bias[(size_t)e * ODIM + nbase + tx * 8];
    float4 bv1 = *(const float4*)&Bias[(size_t)e * ODIM + nbase + tx * 8 + 4];
    float bb[8] = {bv0.x, bv0.y, bv0.z, bv0.w, bv1.x, bv1.y, bv1.z, bv1.w};

#pragma unroll
    for (int i = 0; i < 8; ++i) {
        int m = mbase + ty * 8 + i;
        float v[8];
#pragma unroll
        for (int j = 0; j < 4; ++j) unpack2(acc[i][j], v[2 * j], v[2 * j + 1]);
        float4 o0, o1;
        o0.x = fmaxf(v[0] + bb[0], 0.f);
        o0.y = fmaxf(v[1] + bb[1], 0.f);
        o0.z = fmaxf(v[2] + bb[2], 0.f);
        o0.w = fmaxf(v[3] + bb[3], 0.f);
        o1.x = fmaxf(v[4] + bb[4], 0.f);
        o1.y = fmaxf(v[5] + bb[5], 0.f);
        o1.z = fmaxf(v[6] + bb[6], 0.f);
        o1.w = fmaxf(v[7] + bb[7], 0.f);
        float* crow = C + (size_t)m * ODIM + nbase + tx * 8;
        *(float4*)(crow + 0) = o0;
        *(float4*)(crow + 4) = o1;
    }
}

// ---------------- combine: out[tok] = w0*y[r0] + w1*y[r1] (fixed order) ----------------
__global__ void combine_kernel(float* __restrict__ out) {
    int tok = blockIdx.x;
    int r0 = g_tok_rows[tok * 2 + 0];
    int r1 = g_tok_rows[tok * 2 + 1];
    float w0 = g_tok_w[tok * 2 + 0];
    float w1 = g_tok_w[tok * 2 + 1];
    const float4* y0 = (const float4*)(g_h1 + (size_t)r0 * ODIM);
    const float4* y1 = (const float4*)(g_h1 + (size_t)r1 * ODIM);
    float4* o = (float4*)(out + (size_t)tok * ODIM);
    for (int c = threadIdx.x; c < ODIM / 4; c += blockDim.x) {
        float4 a = y0[c], b = y1[c];
        float4 r;
        r.x = w0 * a.x + w1 * b.x;
        r.y = w0 * a.y + w1 * b.y;
        r.z = w0 * a.z + w1 * b.z;
        r.w = w0 * a.w + w1 * b.w;
        o[c] = r;
    }
}

// ---------------- launch ----------------
extern "C" void kernel_launch(void* const* d_in, const int* in_sizes, int n_in,
                              void* d_out, int out_size) {
    const float* x  = (const float*)d_in[0];
    const float* gw = (const float*)d_in[1];
    const float* gb = (const float*)d_in[2];
    const float* w1 = (const float*)d_in[3];
    const float* b1 = (const float*)d_in[4];
    const float* w2 = (const float*)d_in[5];
    const float* b2 = (const float*)d_in[6];
    const float* w3 = (const float*)d_in[7];
    const float* b3 = (const float*)d_in[8];
    float* out = (float*)d_out;

    init_kernel<<<(MAXROWS + 255) / 256, 256>>>();
    gate_kernel<<<N_TOK / 8, 256>>>(x, gw, gb);
    offsets_kernel<<<1, 32>>>();
    scatter_kernel<<<(N_TOK * TOPK + 255) / 256, 256>>>();

    dim3 grid(ODIM / BN, MTILES);
    moe_gemm<0><<<grid, 256>>>(x, w1, b1);
    moe_gemm<1><<<grid, 256>>>(x, w2, b2);
    moe_gemm<2><<<grid, 256>>>(x, w3, b3);

    combine_kernel<<<N_TOK, 128>>>(out);
}

// round 9
// speedup vs baseline: 2.2974x; 2.2420x over previous
#include <cuda_runtime.h>
#include <cuda_bf16.h>
#include <stdint.h>

// ---------------- problem constants ----------------
#define N_TOK 4096
#define DIM   512
#define ODIM  512
#define NEXP  8
#define TOPK  2

// ---------------- GEMM tiling ----------------
#define BM 128
#define BN 128
#define BK 32
#define NCH (DIM / BK)                      // 16 k-chunks
#define MAXROWS (N_TOK * TOPK + NEXP * BM)  // 9216
#define MTILES  (MAXROWS / BM)              // 72
#define NTILES  (ODIM / BN)                 // 4

typedef unsigned int u32;
typedef unsigned long long u64;

// ---------------- device scratch ----------------
__device__ int   g_counts[NEXP];
__device__ int   g_offsets[NEXP + 1];
__device__ int   g_cursor[NEXP];
__device__ int   g_row_token[MAXROWS];
__device__ int   g_top_e[N_TOK * TOPK];
__device__ int   g_tok_rows[N_TOK * TOPK];
__device__ float g_tok_w[N_TOK * TOPK];
__device__ float g_y[(size_t)MAXROWS * ODIM];
// transposed weights, bf16 hi/lo: [(layer*NEXP+e)*ODIM + n][k]
__device__ __nv_bfloat16 g_wh[(size_t)3 * NEXP * ODIM * DIM];
__device__ __nv_bfloat16 g_wl[(size_t)3 * NEXP * ODIM * DIM];
// activations, bf16 hi/lo, ping-pong
__device__ __nv_bfloat16 g_ah[2][(size_t)MAXROWS * DIM];
__device__ __nv_bfloat16 g_al[2][(size_t)MAXROWS * DIM];

// ---------------- PTX helpers ----------------
__device__ __forceinline__ u32 smem_u32(const void* p) {
    u32 a;
    asm("{ .reg .u64 t; cvta.to.shared.u64 t, %1; cvt.u32.u64 %0, t; }" : "=r"(a) : "l"(p));
    return a;
}
__device__ __forceinline__ void cp16(u32 dst, const void* src) {
    asm volatile("cp.async.cg.shared.global [%0], [%1], 16;" :: "r"(dst), "l"(src) : "memory");
}
__device__ __forceinline__ void cp_commit() {
    asm volatile("cp.async.commit_group;" ::: "memory");
}
template <int N>
__device__ __forceinline__ void cp_wait() {
    asm volatile("cp.async.wait_group %0;" :: "n"(N) : "memory");
}
#define LDM_X4(d, addr)                                                        \
    asm volatile("ldmatrix.sync.aligned.m8n8.x4.shared.b16 {%0,%1,%2,%3}, [%4];" \
        : "=r"((d)[0]), "=r"((d)[1]), "=r"((d)[2]), "=r"((d)[3]) : "r"(addr))
#define MMA16816(c, a, bv0, bv1)                                               \
    asm volatile("mma.sync.aligned.m16n8k16.row.col.f32.bf16.bf16.f32 "        \
        "{%0,%1,%2,%3}, {%4,%5,%6,%7}, {%8,%9}, {%0,%1,%2,%3};"                \
        : "+f"((c)[0]), "+f"((c)[1]), "+f"((c)[2]), "+f"((c)[3])               \
        : "r"((a)[0]), "r"((a)[1]), "r"((a)[2]), "r"((a)[3]), "r"(bv0), "r"(bv1))

__device__ __forceinline__ u32 pack_bf16x2(__nv_bfloat16 a, __nv_bfloat16 b) {
    return (u32)__bfloat16_as_ushort(a) | ((u32)__bfloat16_as_ushort(b) << 16);
}
// swizzled byte offset of (row r, 16B-chunk c) within a 128x32-bf16 tile
__device__ __forceinline__ u32 swz_off(int r, int c) {
    return (u32)(r * 64 + ((c ^ ((r >> 1) & 3)) << 4));
}

// ---------------- init ----------------
__global__ void init_kernel() {
    int i = blockIdx.x * blockDim.x + threadIdx.x;
    if (i < NEXP) g_counts[i] = 0;
    if (i < MAXROWS) g_row_token[i] = -1;
}

// ---------------- gating: one warp per token ----------------
__global__ void gate_kernel(const float* __restrict__ x,
                            const float* __restrict__ gw,
                            const float* __restrict__ gb) {
    int warp = (blockIdx.x * blockDim.x + threadIdx.x) >> 5;
    int lane = threadIdx.x & 31;
    if (warp >= N_TOK) return;
    const float* xr = x + (size_t)warp * DIM;

    float acc[NEXP];
#pragma unroll
    for (int e = 0; e < NEXP; ++e) acc[e] = 0.f;
    for (int i = lane; i < DIM; i += 32) {
        float xv = xr[i];
        const float4* g4 = (const float4*)(gw + (size_t)i * NEXP);
        float4 a = g4[0], b = g4[1];
        acc[0] += xv * a.x; acc[1] += xv * a.y; acc[2] += xv * a.z; acc[3] += xv * a.w;
        acc[4] += xv * b.x; acc[5] += xv * b.y; acc[6] += xv * b.z; acc[7] += xv * b.w;
    }
#pragma unroll
    for (int e = 0; e < NEXP; ++e)
#pragma unroll
        for (int off = 16; off; off >>= 1)
            acc[e] += __shfl_xor_sync(0xffffffffu, acc[e], off);

    if (lane == 0) {
        float lg[NEXP], mx = -1e30f;
#pragma unroll
        for (int e = 0; e < NEXP; ++e) { lg[e] = acc[e] + gb[e]; mx = fmaxf(mx, lg[e]); }
        float p[NEXP], s = 0.f;
#pragma unroll
        for (int e = 0; e < NEXP; ++e) { p[e] = expf(lg[e] - mx); s += p[e]; }
        float inv = 1.0f / s;
        int i0 = 0;
#pragma unroll
        for (int e = 1; e < NEXP; ++e) if (lg[e] > lg[i0]) i0 = e;
        int i1 = -1;
#pragma unroll
        for (int e = 0; e < NEXP; ++e)
            if (e != i0 && (i1 < 0 || lg[e] > lg[i1])) i1 = e;
        // Faithful quirk: slot j combine weight is probs[n, j]
        g_top_e[warp * 2 + 0] = i0;
        g_top_e[warp * 2 + 1] = i1;
        g_tok_w[warp * 2 + 0] = p[0] * inv;
        g_tok_w[warp * 2 + 1] = p[1] * inv;
        atomicAdd(&g_counts[i0], 1);
        atomicAdd(&g_counts[i1], 1);
    }
}

// ---------------- offsets (padded to BM per expert) ----------------
__global__ void offsets_kernel() {
    int t = threadIdx.x;
    if (t == 0) {
        int off = 0;
#pragma unroll
        for (int e = 0; e < NEXP; ++e) {
            g_offsets[e] = off;
            off += ((g_counts[e] + BM - 1) / BM) * BM;
        }
        g_offsets[NEXP] = off;
    }
    if (t < NEXP) g_cursor[t] = 0;
}

// ---------------- scatter ----------------
__global__ void scatter_kernel() {
    int i = blockIdx.x * blockDim.x + threadIdx.x;
    if (i >= N_TOK * TOPK) return;
    int e = g_top_e[i];
    int pos = atomicAdd(&g_cursor[e], 1);
    int r = g_offsets[e] + pos;
    g_row_token[r] = i >> 1;
    g_tok_rows[i] = r;
}

// ---------------- weight convert: transpose + bf16 hi/lo split ----------------
__global__ void convert_w_kernel(const float* __restrict__ w1,
                                 const float* __restrict__ w2,
                                 const float* __restrict__ w3) {
    __shared__ __nv_bfloat16 sh[64][66];
    __shared__ __nv_bfloat16 sl[64][66];
    int l = blockIdx.z, e = blockIdx.y;
    int kt = blockIdx.x >> 3, nt = blockIdx.x & 7;
    const float* W = (l == 0) ? w1 : (l == 1) ? w2 : w3;
    int kb = kt * 64, nb = nt * 64;
    int tid = threadIdx.x;
    {
        int nn = tid & 63, k0 = tid >> 6;
#pragma unroll
        for (int i = 0; i < 16; ++i) {
            int kk = k0 + i * 4;
            float w = W[((size_t)e * DIM + kb + kk) * ODIM + nb + nn];
            __nv_bfloat16 h = __float2bfloat16_rn(w);
            __nv_bfloat16 lo = __float2bfloat16_rn(w - __bfloat162float(h));
            sh[kk][nn] = h;
            sl[kk][nn] = lo;
        }
    }
    __syncthreads();
    {
        size_t ob = (size_t)(l * NEXP + e) * ODIM;
        int kk = tid & 63, n0 = tid >> 6;
#pragma unroll
        for (int i = 0; i < 16; ++i) {
            int nn = n0 + i * 4;
            g_wh[(ob + nb + nn) * DIM + kb + kk] = sh[kk][nn];
            g_wl[(ob + nb + nn) * DIM + kb + kk] = sl[kk][nn];
        }
    }
}

// ---------------- activation convert (layer0, gathered) ----------------
__global__ void convert_a_kernel(const float* __restrict__ x) {
    int r = blockIdx.x;
    int tok = g_row_token[r];
    int c = threadIdx.x;
    float4 v = make_float4(0.f, 0.f, 0.f, 0.f);
    if (tok >= 0) v = *(const float4*)(x + (size_t)tok * DIM + c * 4);
    __nv_bfloat16 h0 = __float2bfloat16_rn(v.x), h1 = __float2bfloat16_rn(v.y);
    __nv_bfloat16 h2 = __float2bfloat16_rn(v.z), h3 = __float2bfloat16_rn(v.w);
    __nv_bfloat16 l0 = __float2bfloat16_rn(v.x - __bfloat162float(h0));
    __nv_bfloat16 l1 = __float2bfloat16_rn(v.y - __bfloat162float(h1));
    __nv_bfloat16 l2 = __float2bfloat16_rn(v.z - __bfloat162float(h2));
    __nv_bfloat16 l3 = __float2bfloat16_rn(v.w - __bfloat162float(h3));
    *(uint2*)(&g_ah[0][(size_t)r * DIM + c * 4]) = make_uint2(pack_bf16x2(h0, h1), pack_bf16x2(h2, h3));
    *(uint2*)(&g_al[0][(size_t)r * DIM + c * 4]) = make_uint2(pack_bf16x2(l0, l1), pack_bf16x2(l2, l3));
}

// ---------------- HMMA grouped GEMM ----------------
// D[m][n] = sum_k A[m][k] * Wt[n][k], bf16 hi/lo 3-pass, fp32 accum.
// LAYER 0: A = g_a*[0] -> g_a*[1]; LAYER 1: g_a*[1] -> g_a*[0]; LAYER 2: g_a*[0] -> g_y
#define OFF_AH 0
#define OFF_AL 8192
#define OFF_BH 16384
#define OFF_BL 24576
#define STAGE_BYTES 32768
#define SMEM_NEED (2 * STAGE_BYTES + 128)

template <int LAYER>
__global__ void __launch_bounds__(256, 2)
moe_gemm_mma(const float* __restrict__ Bias) {
    const __nv_bfloat16* Ah = g_ah[(LAYER == 1) ? 1 : 0];
    const __nv_bfloat16* Al = g_al[(LAYER == 1) ? 1 : 0];
    __nv_bfloat16* Oh = (LAYER == 0) ? g_ah[1] : g_ah[0];
    __nv_bfloat16* Ol = (LAYER == 0) ? g_al[1] : g_al[0];

    int total = g_offsets[NEXP];
    int mbase = blockIdx.y * BM;
    if (mbase >= total) return;
    int e = 0;
    while (e < NEXP - 1 && mbase >= g_offsets[e + 1]) e++;
    int nbase = blockIdx.x * BN;

    extern __shared__ char smraw[];
    u32 sraw = smem_u32(smraw);
    u32 sbase = (sraw + 127u) & ~127u;

    int tid = threadIdx.x;
    int wid = tid >> 5, lid = tid & 31;
    int wm = wid & 3, wn = wid >> 2;

    const __nv_bfloat16* Whp = g_wh + ((size_t)(LAYER * NEXP + e) * ODIM + nbase) * DIM;
    const __nv_bfloat16* Wlp = g_wl + ((size_t)(LAYER * NEXP + e) * ODIM + nbase) * DIM;
    const __nv_bfloat16* Ahp = Ah + (size_t)mbase * DIM;
    const __nv_bfloat16* Alp = Al + (size_t)mbase * DIM;

    // per-thread cp.async indices: 512 16B-chunks per region, 2 per thread
    int r0 = tid >> 2, c0 = tid & 3;          // g = tid
    int r1 = (tid + 256) >> 2, c1 = tid & 3;  // g = tid + 256
    u32 d0 = swz_off(r0, c0), d1 = swz_off(r1, c1);
    size_t s0 = (size_t)r0 * DIM + c0 * 8;
    size_t s1 = (size_t)r1 * DIM + c1 * 8;

    float acc[2][8][4];
#pragma unroll
    for (int i = 0; i < 2; ++i)
#pragma unroll
        for (int j = 0; j < 8; ++j)
#pragma unroll
            for (int q = 0; q < 4; ++q) acc[i][j][q] = 0.f;

#define PREFETCH(ch) do {                                                      \
    u32 sb = sbase + ((ch) & 1) * STAGE_BYTES;                                 \
    int kk = (ch) * BK;                                                        \
    cp16(sb + OFF_AH + d0, Ahp + s0 + kk);                                     \
    cp16(sb + OFF_AH + d1, Ahp + s1 + kk);                                     \
    cp16(sb + OFF_AL + d0, Alp + s0 + kk);                                     \
    cp16(sb + OFF_AL + d1, Alp + s1 + kk);                                     \
    cp16(sb + OFF_BH + d0, Whp + s0 + kk);                                     \
    cp16(sb + OFF_BH + d1, Whp + s1 + kk);                                     \
    cp16(sb + OFF_BL + d0, Wlp + s0 + kk);                                     \
    cp16(sb + OFF_BL + d1, Wlp + s1 + kk);                                     \
    cp_commit();                                                               \
} while (0)

    PREFETCH(0);

    for (int ch = 0; ch < NCH; ++ch) {
        if (ch + 1 < NCH) { PREFETCH(ch + 1); cp_wait<1>(); }
        else              { cp_wait<0>(); }
        __syncthreads();

        u32 sb = sbase + (ch & 1) * STAGE_BYTES;
#pragma unroll
        for (int s = 0; s < 2; ++s) {
            u32 ah[2][4], al[2][4];
#pragma unroll
            for (int mt = 0; mt < 2; ++mt) {
                int r = wm * 32 + mt * 16 + (lid & 15);
                int chunk = s * 2 + (lid >> 4);
                u32 off = swz_off(r, chunk);
                LDM_X4(ah[mt], sb + OFF_AH + off);
                LDM_X4(al[mt], sb + OFF_AL + off);
            }
#pragma unroll
            for (int p = 0; p < 4; ++p) {
                int n = wn * 64 + p * 16 + ((lid >> 4) << 3) + (lid & 7);
                int chunk = s * 2 + ((lid >> 3) & 1);
                u32 off = swz_off(n, chunk);
                u32 bh[4], bl[4];
                LDM_X4(bh, sb + OFF_BH + off);
                LDM_X4(bl, sb + OFF_BL + off);
#pragma unroll
                for (int mt = 0; mt < 2; ++mt) {
                    MMA16816(acc[mt][2 * p + 0], ah[mt], bh[0], bh[1]);
                    MMA16816(acc[mt][2 * p + 0], ah[mt], bl[0], bl[1]);
                    MMA16816(acc[mt][2 * p + 0], al[mt], bh[0], bh[1]);
                    MMA16816(acc[mt][2 * p + 1], ah[mt], bh[2], bh[3]);
                    MMA16816(acc[mt][2 * p + 1], ah[mt], bl[2], bl[3]);
                    MMA16816(acc[mt][2 * p + 1], al[mt], bh[2], bh[3]);
                }
            }
        }
        __syncthreads();
    }
#undef PREFETCH

    // epilogue: bias + relu, write next layer bf16 hi/lo (or fp32 y)
#pragma unroll
    for (int mt = 0; mt < 2; ++mt) {
#pragma unroll
        for (int nt = 0; nt < 8; ++nt) {
            int row = mbase + wm * 32 + mt * 16 + (lid >> 2);
            int n0 = nbase + wn * 64 + nt * 8 + (lid & 3) * 2;
            float bb0 = __ldg(Bias + e * ODIM + n0);
            float bb1 = __ldg(Bias + e * ODIM + n0 + 1);
            float v00 = fmaxf(acc[mt][nt][0] + bb0, 0.f);
            float v01 = fmaxf(acc[mt][nt][1] + bb1, 0.f);
            float v10 = fmaxf(acc[mt][nt][2] + bb0, 0.f);
            float v11 = fmaxf(acc[mt][nt][3] + bb1, 0.f);
            if (LAYER < 2) {
                __nv_bfloat16 h00 = __float2bfloat16_rn(v00);
                __nv_bfloat16 h01 = __float2bfloat16_rn(v01);
                __nv_bfloat16 h10 = __float2bfloat16_rn(v10);
                __nv_bfloat16 h11 = __float2bfloat16_rn(v11);
                __nv_bfloat16 l00 = __float2bfloat16_rn(v00 - __bfloat162float(h00));
                __nv_bfloat16 l01 = __float2bfloat16_rn(v01 - __bfloat162float(h01));
                __nv_bfloat16 l10 = __float2bfloat16_rn(v10 - __bfloat162float(h10));
                __nv_bfloat16 l11 = __float2bfloat16_rn(v11 - __bfloat162float(h11));
                *(u32*)(Oh + (size_t)row * DIM + n0)       = pack_bf16x2(h00, h01);
                *(u32*)(Ol + (size_t)row * DIM + n0)       = pack_bf16x2(l00, l01);
                *(u32*)(Oh + (size_t)(row + 8) * DIM + n0) = pack_bf16x2(h10, h11);
                *(u32*)(Ol + (size_t)(row + 8) * DIM + n0) = pack_bf16x2(l10, l11);
            } else {
                *(float2*)(g_y + (size_t)row * ODIM + n0)       = make_float2(v00, v01);
                *(float2*)(g_y + (size_t)(row + 8) * ODIM + n0) = make_float2(v10, v11);
            }
        }
    }
}

// ---------------- combine ----------------
__global__ void combine_kernel(float* __restrict__ out) {
    int tok = blockIdx.x;
    int r0 = g_tok_rows[tok * 2 + 0];
    int r1 = g_tok_rows[tok * 2 + 1];
    float w0 = g_tok_w[tok * 2 + 0];
    float w1 = g_tok_w[tok * 2 + 1];
    const float4* y0 = (const float4*)(g_y + (size_t)r0 * ODIM);
    const float4* y1 = (const float4*)(g_y + (size_t)r1 * ODIM);
    float4* o = (float4*)(out + (size_t)tok * ODIM);
    for (int c = threadIdx.x; c < ODIM / 4; c += blockDim.x) {
        float4 a = y0[c], b = y1[c];
        o[c] = make_float4(w0 * a.x + w1 * b.x, w0 * a.y + w1 * b.y,
                           w0 * a.z + w1 * b.z, w0 * a.w + w1 * b.w);
    }
}

// ---------------- launch ----------------
extern "C" void kernel_launch(void* const* d_in, const int* in_sizes, int n_in,
                              void* d_out, int out_size) {
    const float* x  = (const float*)d_in[0];
    const float* gw = (const float*)d_in[1];
    const float* gb = (const float*)d_in[2];
    const float* w1 = (const float*)d_in[3];
    const float* b1 = (const float*)d_in[4];
    const float* w2 = (const float*)d_in[5];
    const float* b2 = (const float*)d_in[6];
    const float* w3 = (const float*)d_in[7];
    const float* b3 = (const float*)d_in[8];
    float* out = (float*)d_out;

    cudaFuncSetAttribute(moe_gemm_mma<0>, cudaFuncAttributeMaxDynamicSharedMemorySize, SMEM_NEED);
    cudaFuncSetAttribute(moe_gemm_mma<1>, cudaFuncAttributeMaxDynamicSharedMemorySize, SMEM_NEED);
    cudaFuncSetAttribute(moe_gemm_mma<2>, cudaFuncAttributeMaxDynamicSharedMemorySize, SMEM_NEED);

    init_kernel<<<(MAXROWS + 255) / 256, 256>>>();
    gate_kernel<<<N_TOK / 8, 256>>>(x, gw, gb);
    offsets_kernel<<<1, 32>>>();
    scatter_kernel<<<(N_TOK * TOPK + 255) / 256, 256>>>();
    convert_w_kernel<<<dim3(64, NEXP, 3), 256>>>(w1, w2, w3);
    convert_a_kernel<<<MAXROWS, 128>>>(x);

    dim3 grid(NTILES, MTILES);
    moe_gemm_mma<0><<<grid, 256, SMEM_NEED>>>(b1);
    moe_gemm_mma<1><<<grid, 256, SMEM_NEED>>>(b2);
    moe_gemm_mma<2><<<grid, 256, SMEM_NEED>>>(b3);

    combine_kernel<<<N_TOK, 128>>>(out);
}

// round 11
// speedup vs baseline: 2.9151x; 1.2689x over previous
#include <cuda_runtime.h>
#include <cuda_fp16.h>
#include <stdint.h>

// ---------------- problem constants ----------------
#define N_TOK 4096
#define DIM   512
#define ODIM  512
#define NEXP  8
#define TOPK  2

// ---------------- GEMM tiling ----------------
#define BM 128
#define BN 128
#define BK 32
#define NCH (DIM / BK)                      // 16 k-chunks
#define MAXROWS (N_TOK * TOPK + NEXP * BM)  // 9216
#define MTILES  (MAXROWS / BM)              // 72
#define NTILES  (ODIM / BN)                 // 4

typedef unsigned int u32;
typedef unsigned long long u64;

// ---------------- device scratch ----------------
__device__ int   g_counts[NEXP];
__device__ int   g_offsets[NEXP + 1];
__device__ int   g_cursor[NEXP];
__device__ int   g_row_token[MAXROWS];
__device__ int   g_top_e[N_TOK * TOPK];
__device__ int   g_tok_rows[N_TOK * TOPK];
__device__ float g_tok_w[N_TOK * TOPK];
__device__ float g_y[(size_t)MAXROWS * ODIM];
// transposed weights, fp16 hi/lo: [(layer*NEXP+e)*ODIM + n][k]
__device__ __half g_wh[(size_t)3 * NEXP * ODIM * DIM];
__device__ __half g_wl[(size_t)3 * NEXP * ODIM * DIM];
// activations, single fp16, ping-pong
__device__ __half g_a[2][(size_t)MAXROWS * DIM];

// ---------------- PTX helpers ----------------
__device__ __forceinline__ u32 smem_u32(const void* p) {
    u32 a;
    asm("{ .reg .u64 t; cvta.to.shared.u64 t, %1; cvt.u32.u64 %0, t; }" : "=r"(a) : "l"(p));
    return a;
}
__device__ __forceinline__ void cp16(u32 dst, const void* src) {
    asm volatile("cp.async.cg.shared.global [%0], [%1], 16;" :: "r"(dst), "l"(src) : "memory");
}
__device__ __forceinline__ void cp_commit() {
    asm volatile("cp.async.commit_group;" ::: "memory");
}
template <int N>
__device__ __forceinline__ void cp_wait() {
    asm volatile("cp.async.wait_group %0;" :: "n"(N) : "memory");
}
#define LDM_X4(d, addr)                                                        \
    asm volatile("ldmatrix.sync.aligned.m8n8.x4.shared.b16 {%0,%1,%2,%3}, [%4];" \
        : "=r"((d)[0]), "=r"((d)[1]), "=r"((d)[2]), "=r"((d)[3]) : "r"(addr))
#define MMA16816(c, a, bv0, bv1)                                               \
    asm volatile("mma.sync.aligned.m16n8k16.row.col.f32.f16.f16.f32 "          \
        "{%0,%1,%2,%3}, {%4,%5,%6,%7}, {%8,%9}, {%0,%1,%2,%3};"                \
        : "+f"((c)[0]), "+f"((c)[1]), "+f"((c)[2]), "+f"((c)[3])               \
        : "r"((a)[0]), "r"((a)[1]), "r"((a)[2]), "r"((a)[3]), "r"(bv0), "r"(bv1))

__device__ __forceinline__ u32 pack_h2(__half a, __half b) {
    return (u32)__half_as_ushort(a) | ((u32)__half_as_ushort(b) << 16);
}
// swizzled byte offset of (row r, 16B-chunk c) within a 128x32-half tile
__device__ __forceinline__ u32 swz_off(int r, int c) {
    return (u32)(r * 64 + ((c ^ ((r >> 1) & 3)) << 4));
}

// ---------------- init ----------------
__global__ void init_kernel() {
    int i = blockIdx.x * blockDim.x + threadIdx.x;
    if (i < NEXP) g_counts[i] = 0;
    if (i < MAXROWS) g_row_token[i] = -1;
}

// ---------------- gating: one warp per token ----------------
__global__ void gate_kernel(const float* __restrict__ x,
                            const float* __restrict__ gw,
                            const float* __restrict__ gb) {
    int warp = (blockIdx.x * blockDim.x + threadIdx.x) >> 5;
    int lane = threadIdx.x & 31;
    if (warp >= N_TOK) return;
    const float* xr = x + (size_t)warp * DIM;

    float acc[NEXP];
#pragma unroll
    for (int e = 0; e < NEXP; ++e) acc[e] = 0.f;
    for (int i = lane; i < DIM; i += 32) {
        float xv = xr[i];
        const float4* g4 = (const float4*)(gw + (size_t)i * NEXP);
        float4 a = g4[0], b = g4[1];
        acc[0] += xv * a.x; acc[1] += xv * a.y; acc[2] += xv * a.z; acc[3] += xv * a.w;
        acc[4] += xv * b.x; acc[5] += xv * b.y; acc[6] += xv * b.z; acc[7] += xv * b.w;
    }
#pragma unroll
    for (int e = 0; e < NEXP; ++e)
#pragma unroll
        for (int off = 16; off; off >>= 1)
            acc[e] += __shfl_xor_sync(0xffffffffu, acc[e], off);

    if (lane == 0) {
        float lg[NEXP], mx = -1e30f;
#pragma unroll
        for (int e = 0; e < NEXP; ++e) { lg[e] = acc[e] + gb[e]; mx = fmaxf(mx, lg[e]); }
        float p[NEXP], s = 0.f;
#pragma unroll
        for (int e = 0; e < NEXP; ++e) { p[e] = expf(lg[e] - mx); s += p[e]; }
        float inv = 1.0f / s;
        int i0 = 0;
#pragma unroll
        for (int e = 1; e < NEXP; ++e) if (lg[e] > lg[i0]) i0 = e;
        int i1 = -1;
#pragma unroll
        for (int e = 0; e < NEXP; ++e)
            if (e != i0 && (i1 < 0 || lg[e] > lg[i1])) i1 = e;
        // Faithful quirk: slot j combine weight is probs[n, j]
        g_top_e[warp * 2 + 0] = i0;
        g_top_e[warp * 2 + 1] = i1;
        g_tok_w[warp * 2 + 0] = p[0] * inv;
        g_tok_w[warp * 2 + 1] = p[1] * inv;
        atomicAdd(&g_counts[i0], 1);
        atomicAdd(&g_counts[i1], 1);
    }
}

// ---------------- offsets (padded to BM per expert) ----------------
__global__ void offsets_kernel() {
    int t = threadIdx.x;
    if (t == 0) {
        int off = 0;
#pragma unroll
        for (int e = 0; e < NEXP; ++e) {
            g_offsets[e] = off;
            off += ((g_counts[e] + BM - 1) / BM) * BM;
        }
        g_offsets[NEXP] = off;
    }
    if (t < NEXP) g_cursor[t] = 0;
}

// ---------------- scatter ----------------
__global__ void scatter_kernel() {
    int i = blockIdx.x * blockDim.x + threadIdx.x;
    if (i >= N_TOK * TOPK) return;
    int e = g_top_e[i];
    int pos = atomicAdd(&g_cursor[e], 1);
    int r = g_offsets[e] + pos;
    g_row_token[r] = i >> 1;
    g_tok_rows[i] = r;
}

// ---------------- weight convert: transpose + fp16 hi/lo split ----------------
__global__ void convert_w_kernel(const float* __restrict__ w1,
                                 const float* __restrict__ w2,
                                 const float* __restrict__ w3) {
    __shared__ __half sh[64][66];
    __shared__ __half sl[64][66];
    int l = blockIdx.z, e = blockIdx.y;
    int kt = blockIdx.x >> 3, nt = blockIdx.x & 7;
    const float* W = (l == 0) ? w1 : (l == 1) ? w2 : w3;
    int kb = kt * 64, nb = nt * 64;
    int tid = threadIdx.x;
    {
        int nn = tid & 63, k0 = tid >> 6;
#pragma unroll
        for (int i = 0; i < 16; ++i) {
            int kk = k0 + i * 4;
            float w = W[((size_t)e * DIM + kb + kk) * ODIM + nb + nn];
            __half h = __float2half_rn(w);
            __half lo = __float2half_rn(w - __half2float(h));
            sh[kk][nn] = h;
            sl[kk][nn] = lo;
        }
    }
    __syncthreads();
    {
        size_t ob = (size_t)(l * NEXP + e) * ODIM;
        int kk = tid & 63, n0 = tid >> 6;
#pragma unroll
        for (int i = 0; i < 16; ++i) {
            int nn = n0 + i * 4;
            g_wh[(ob + nb + nn) * DIM + kb + kk] = sh[kk][nn];
            g_wl[(ob + nb + nn) * DIM + kb + kk] = sl[kk][nn];
        }
    }
}

// ---------------- activation convert (layer0, gathered) ----------------
__global__ void convert_a_kernel(const float* __restrict__ x) {
    int r = blockIdx.x;
    int tok = g_row_token[r];
    int c = threadIdx.x;
    float4 v = make_float4(0.f, 0.f, 0.f, 0.f);
    if (tok >= 0) v = *(const float4*)(x + (size_t)tok * DIM + c * 4);
    *(uint2*)(&g_a[0][(size_t)r * DIM + c * 4]) =
        make_uint2(pack_h2(__float2half_rn(v.x), __float2half_rn(v.y)),
                   pack_h2(__float2half_rn(v.z), __float2half_rn(v.w)));
}

// ---------------- HMMA grouped GEMM ----------------
// D[m][n] = sum_k A[m][k] * (Wh+Wl)[n][k], fp16 2-pass, fp32 accum.
// LAYER 0: A = g_a[0] -> g_a[1]; LAYER 1: g_a[1] -> g_a[0]; LAYER 2: g_a[0] -> g_y
#define OFF_A  0
#define OFF_BH 8192
#define OFF_BL 16384
#define STAGE_BYTES 24576
#define NSTAGE 3
#define SMEM_NEED (NSTAGE * STAGE_BYTES + 128)

template <int LAYER>
__global__ void __launch_bounds__(256, 2)
moe_gemm_mma(const float* __restrict__ Bias) {
    const __half* Ain = g_a[(LAYER == 1) ? 1 : 0];
    __half* Oa = (LAYER == 0) ? g_a[1] : g_a[0];

    int total = g_offsets[NEXP];
    int mbase = blockIdx.y * BM;
    if (mbase >= total) return;
    int e = 0;
    while (e < NEXP - 1 && mbase >= g_offsets[e + 1]) e++;
    int nbase = blockIdx.x * BN;

    extern __shared__ char smraw[];
    u32 sraw = smem_u32(smraw);
    u32 sbase = (sraw + 127u) & ~127u;

    int tid = threadIdx.x;
    int wid = tid >> 5, lid = tid & 31;
    int wm = wid & 3, wn = wid >> 2;

    const __half* Whp = g_wh + ((size_t)(LAYER * NEXP + e) * ODIM + nbase) * DIM;
    const __half* Wlp = g_wl + ((size_t)(LAYER * NEXP + e) * ODIM + nbase) * DIM;
    const __half* Ahp = Ain + (size_t)mbase * DIM;

    // per-thread cp.async indices: 512 16B-chunks per region, 2 per thread
    int r0 = tid >> 2, c0 = tid & 3;
    int r1 = (tid + 256) >> 2, c1 = tid & 3;
    u32 d0 = swz_off(r0, c0), d1 = swz_off(r1, c1);
    size_t s0 = (size_t)r0 * DIM + c0 * 8;
    size_t s1 = (size_t)r1 * DIM + c1 * 8;

    float acc[2][8][4];
#pragma unroll
    for (int i = 0; i < 2; ++i)
#pragma unroll
        for (int j = 0; j < 8; ++j)
#pragma unroll
            for (int q = 0; q < 4; ++q) acc[i][j][q] = 0.f;

#define PREFETCH(ch) do {                                                      \
    u32 sb = sbase + ((ch) % NSTAGE) * STAGE_BYTES;                            \
    int kk = (ch) * BK;                                                        \
    cp16(sb + OFF_A  + d0, Ahp + s0 + kk);                                     \
    cp16(sb + OFF_A  + d1, Ahp + s1 + kk);                                     \
    cp16(sb + OFF_BH + d0, Whp + s0 + kk);                                     \
    cp16(sb + OFF_BH + d1, Whp + s1 + kk);                                     \
    cp16(sb + OFF_BL + d0, Wlp + s0 + kk);                                     \
    cp16(sb + OFF_BL + d1, Wlp + s1 + kk);                                     \
    cp_commit();                                                               \
} while (0)

    PREFETCH(0);
    PREFETCH(1);

    for (int ch = 0; ch < NCH; ++ch) {
        if (ch + 2 < NCH) { PREFETCH(ch + 2); cp_wait<2>(); }
        else if (ch + 1 < NCH) { cp_wait<1>(); }
        else { cp_wait<0>(); }
        __syncthreads();

        u32 sb = sbase + (ch % NSTAGE) * STAGE_BYTES;
#pragma unroll
        for (int s = 0; s < 2; ++s) {
            u32 af[2][4];
#pragma unroll
            for (int mt = 0; mt < 2; ++mt) {
                int r = wm * 32 + mt * 16 + (lid & 15);
                int chunk = s * 2 + (lid >> 4);
                LDM_X4(af[mt], sb + OFF_A + swz_off(r, chunk));
            }
#pragma unroll
            for (int p = 0; p < 4; ++p) {
                int n = wn * 64 + p * 16 + ((lid >> 4) << 3) + (lid & 7);
                int chunk = s * 2 + ((lid >> 3) & 1);
                u32 off = swz_off(n, chunk);
                u32 bh[4], bl[4];
                LDM_X4(bh, sb + OFF_BH + off);
                LDM_X4(bl, sb + OFF_BL + off);
#pragma unroll
                for (int mt = 0; mt < 2; ++mt) {
                    MMA16816(acc[mt][2 * p + 0], af[mt], bh[0], bh[1]);
                    MMA16816(acc[mt][2 * p + 0], af[mt], bl[0], bl[1]);
                    MMA16816(acc[mt][2 * p + 1], af[mt], bh[2], bh[3]);
                    MMA16816(acc[mt][2 * p + 1], af[mt], bl[2], bl[3]);
                }
            }
        }
        __syncthreads();
    }
#undef PREFETCH

    // epilogue: bias + relu, write next layer fp16 (or fp32 y)
#pragma unroll
    for (int mt = 0; mt < 2; ++mt) {
#pragma unroll
        for (int nt = 0; nt < 8; ++nt) {
            int row = mbase + wm * 32 + mt * 16 + (lid >> 2);
            int n0 = nbase + wn * 64 + nt * 8 + (lid & 3) * 2;
            float bb0 = __ldg(Bias + e * ODIM + n0);
            float bb1 = __ldg(Bias + e * ODIM + n0 + 1);
            float v00 = fmaxf(acc[mt][nt][0] + bb0, 0.f);
            float v01 = fmaxf(acc[mt][nt][1] + bb1, 0.f);
            float v10 = fmaxf(acc[mt][nt][2] + bb0, 0.f);
            float v11 = fmaxf(acc[mt][nt][3] + bb1, 0.f);
            if (LAYER < 2) {
                *(u32*)(Oa + (size_t)row * DIM + n0) =
                    pack_h2(__float2half_rn(v00), __float2half_rn(v01));
                *(u32*)(Oa + (size_t)(row + 8) * DIM + n0) =
                    pack_h2(__float2half_rn(v10), __float2half_rn(v11));
            } else {
                *(float2*)(g_y + (size_t)row * ODIM + n0)       = make_float2(v00, v01);
                *(float2*)(g_y + (size_t)(row + 8) * ODIM + n0) = make_float2(v10, v11);
            }
        }
    }
}

// ---------------- combine ----------------
__global__ void combine_kernel(float* __restrict__ out) {
    int tok = blockIdx.x;
    int r0 = g_tok_rows[tok * 2 + 0];
    int r1 = g_tok_rows[tok * 2 + 1];
    float w0 = g_tok_w[tok * 2 + 0];
    float w1 = g_tok_w[tok * 2 + 1];
    const float4* y0 = (const float4*)(g_y + (size_t)r0 * ODIM);
    const float4* y1 = (const float4*)(g_y + (size_t)r1 * ODIM);
    float4* o = (float4*)(out + (size_t)tok * ODIM);
    for (int c = threadIdx.x; c < ODIM / 4; c += blockDim.x) {
        float4 a = y0[c], b = y1[c];
        o[c] = make_float4(w0 * a.x + w1 * b.x, w0 * a.y + w1 * b.y,
                           w0 * a.z + w1 * b.z, w0 * a.w + w1 * b.w);
    }
}

// ---------------- launch ----------------
extern "C" void kernel_launch(void* const* d_in, const int* in_sizes, int n_in,
                              void* d_out, int out_size) {
    const float* x  = (const float*)d_in[0];
    const float* gw = (const float*)d_in[1];
    const float* gb = (const float*)d_in[2];
    const float* w1 = (const float*)d_in[3];
    const float* b1 = (const float*)d_in[4];
    const float* w2 = (const float*)d_in[5];
    const float* b2 = (const float*)d_in[6];
    const float* w3 = (const float*)d_in[7];
    const float* b3 = (const float*)d_in[8];
    float* out = (float*)d_out;

    cudaFuncSetAttribute(moe_gemm_mma<0>, cudaFuncAttributeMaxDynamicSharedMemorySize, SMEM_NEED);
    cudaFuncSetAttribute(moe_gemm_mma<1>, cudaFuncAttributeMaxDynamicSharedMemorySize, SMEM_NEED);
    cudaFuncSetAttribute(moe_gemm_mma<2>, cudaFuncAttributeMaxDynamicSharedMemorySize, SMEM_NEED);

    init_kernel<<<(MAXROWS + 255) / 256, 256>>>();
    gate_kernel<<<N_TOK / 8, 256>>>(x, gw, gb);
    offsets_kernel<<<1, 32>>>();
    scatter_kernel<<<(N_TOK * TOPK + 255) / 256, 256>>>();
    convert_w_kernel<<<dim3(64, NEXP, 3), 256>>>(w1, w2, w3);
    convert_a_kernel<<<MAXROWS, 128>>>(x);

    dim3 grid(NTILES, MTILES);
    moe_gemm_mma<0><<<grid, 256, SMEM_NEED>>>(b1);
    moe_gemm_mma<1><<<grid, 256, SMEM_NEED>>>(b2);
    moe_gemm_mma<2><<<grid, 256, SMEM_NEED>>>(b3);

    combine_kernel<<<N_TOK, 128>>>(out);
}

// round 12
// speedup vs baseline: 3.7673x; 1.2923x over previous
#include <cuda_runtime.h>
#include <cuda_fp16.h>
#include <stdint.h>

// ---------------- problem constants ----------------
#define N_TOK 4096
#define DIM   512
#define ODIM  512
#define NEXP  8
#define TOPK  2

// ---------------- GEMM tiling ----------------
#define BM 128
#define BN 128
#define BK 32
#define NCH (DIM / BK)                      // 16 k-chunks
#define MAXROWS (N_TOK * TOPK + NEXP * BM)  // 9216
#define MTILES  (MAXROWS / BM)              // 72
#define NTILES  (ODIM / BN)                 // 4

typedef unsigned int u32;
typedef unsigned long long u64;

// ---------------- device scratch ----------------
__device__ int   g_counts[NEXP];
__device__ int   g_offsets[NEXP + 1];
__device__ int   g_row_token[MAXROWS];
__device__ int   g_top_e[N_TOK * TOPK];
__device__ int   g_tok_rows[N_TOK * TOPK];
__device__ float g_tok_w[N_TOK * TOPK];
__device__ float g_y[(size_t)MAXROWS * ODIM];
// transposed weights, fp16: [(layer*NEXP+e)*ODIM + n][k]
__device__ __half g_w[(size_t)3 * NEXP * ODIM * DIM];
// activations, fp16, ping-pong
__device__ __half g_a[2][(size_t)MAXROWS * DIM];

// ---------------- PTX helpers ----------------
__device__ __forceinline__ u32 smem_u32(const void* p) {
    u32 a;
    asm("{ .reg .u64 t; cvta.to.shared.u64 t, %1; cvt.u32.u64 %0, t; }" : "=r"(a) : "l"(p));
    return a;
}
__device__ __forceinline__ void cp16(u32 dst, const void* src) {
    asm volatile("cp.async.cg.shared.global [%0], [%1], 16;" :: "r"(dst), "l"(src) : "memory");
}
__device__ __forceinline__ void cp_commit() {
    asm volatile("cp.async.commit_group;" ::: "memory");
}
template <int N>
__device__ __forceinline__ void cp_wait() {
    asm volatile("cp.async.wait_group %0;" :: "n"(N) : "memory");
}
#define LDM_X4(d, addr)                                                        \
    asm volatile("ldmatrix.sync.aligned.m8n8.x4.shared.b16 {%0,%1,%2,%3}, [%4];" \
        : "=r"((d)[0]), "=r"((d)[1]), "=r"((d)[2]), "=r"((d)[3]) : "r"(addr))
#define MMA16816(c, a, bv0, bv1)                                               \
    asm volatile("mma.sync.aligned.m16n8k16.row.col.f32.f16.f16.f32 "          \
        "{%0,%1,%2,%3}, {%4,%5,%6,%7}, {%8,%9}, {%0,%1,%2,%3};"                \
        : "+f"((c)[0]), "+f"((c)[1]), "+f"((c)[2]), "+f"((c)[3])               \
        : "r"((a)[0]), "r"((a)[1]), "r"((a)[2]), "r"((a)[3]), "r"(bv0), "r"(bv1))

__device__ __forceinline__ u32 pack_h2(__half a, __half b) {
    return (u32)__half_as_ushort(a) | ((u32)__half_as_ushort(b) << 16);
}
// swizzled byte offset of (row r, 16B-chunk c) within a 128x32-half tile
__device__ __forceinline__ u32 swz_off(int r, int c) {
    return (u32)(r * 64 + ((c ^ ((r >> 1) & 3)) << 4));
}

// ---------------- init ----------------
__global__ void init_kernel() {
    int i = blockIdx.x * blockDim.x + threadIdx.x;
    if (i < NEXP) g_counts[i] = 0;
    if (i < MAXROWS) g_row_token[i] = -1;
}

// ---------------- gating: one warp per token ----------------
__global__ void gate_kernel(const float* __restrict__ x,
                            const float* __restrict__ gw,
                            const float* __restrict__ gb) {
    int warp = (blockIdx.x * blockDim.x + threadIdx.x) >> 5;
    int lane = threadIdx.x & 31;
    if (warp >= N_TOK) return;
    const float* xr = x + (size_t)warp * DIM;

    float acc[NEXP];
#pragma unroll
    for (int e = 0; e < NEXP; ++e) acc[e] = 0.f;
    for (int i = lane; i < DIM; i += 32) {
        float xv = xr[i];
        const float4* g4 = (const float4*)(gw + (size_t)i * NEXP);
        float4 a = g4[0], b = g4[1];
        acc[0] += xv * a.x; acc[1] += xv * a.y; acc[2] += xv * a.z; acc[3] += xv * a.w;
        acc[4] += xv * b.x; acc[5] += xv * b.y; acc[6] += xv * b.z; acc[7] += xv * b.w;
    }
#pragma unroll
    for (int e = 0; e < NEXP; ++e)
#pragma unroll
        for (int off = 16; off; off >>= 1)
            acc[e] += __shfl_xor_sync(0xffffffffu, acc[e], off);

    if (lane == 0) {
        float lg[NEXP], mx = -1e30f;
#pragma unroll
        for (int e = 0; e < NEXP; ++e) { lg[e] = acc[e] + gb[e]; mx = fmaxf(mx, lg[e]); }
        float p[NEXP], s = 0.f;
#pragma unroll
        for (int e = 0; e < NEXP; ++e) { p[e] = expf(lg[e] - mx); s += p[e]; }
        float inv = 1.0f / s;
        int i0 = 0;
#pragma unroll
        for (int e = 1; e < NEXP; ++e) if (lg[e] > lg[i0]) i0 = e;
        int i1 = -1;
#pragma unroll
        for (int e = 0; e < NEXP; ++e)
            if (e != i0 && (i1 < 0 || lg[e] > lg[i1])) i1 = e;
        // Faithful quirk: slot j combine weight is probs[n, j]
        g_top_e[warp * 2 + 0] = i0;
        g_top_e[warp * 2 + 1] = i1;
        g_tok_w[warp * 2 + 0] = p[0] * inv;
        g_tok_w[warp * 2 + 1] = p[1] * inv;
        atomicAdd(&g_counts[i0], 1);
        atomicAdd(&g_counts[i1], 1);
    }
}

// ---------------- route: offsets (padded to BM) + scatter, single block ----------------
__global__ void route_kernel() {
    __shared__ int soff[NEXP];
    __shared__ int scur[NEXP];
    int tid = threadIdx.x;
    if (tid == 0) {
        int off = 0;
#pragma unroll
        for (int e = 0; e < NEXP; ++e) {
            g_offsets[e] = off;
            soff[e] = off;
            off += ((g_counts[e] + BM - 1) / BM) * BM;
        }
        g_offsets[NEXP] = off;
    }
    if (tid < NEXP) scur[tid] = 0;
    __syncthreads();
    for (int i = tid; i < N_TOK * TOPK; i += blockDim.x) {
        int e = g_top_e[i];
        int pos = atomicAdd(&scur[e], 1);
        int r = soff[e] + pos;
        g_row_token[r] = i >> 1;
        g_tok_rows[i] = r;
    }
}

// ---------------- weight convert: transpose + fp16 ----------------
__global__ void convert_w_kernel(const float* __restrict__ w1,
                                 const float* __restrict__ w2,
                                 const float* __restrict__ w3) {
    __shared__ __half sh[64][66];
    int l = blockIdx.z, e = blockIdx.y;
    int kt = blockIdx.x >> 3, nt = blockIdx.x & 7;
    const float* W = (l == 0) ? w1 : (l == 1) ? w2 : w3;
    int kb = kt * 64, nb = nt * 64;
    int tid = threadIdx.x;
    {
        int nn = tid & 63, k0 = tid >> 6;
#pragma unroll
        for (int i = 0; i < 16; ++i) {
            int kk = k0 + i * 4;
            sh[kk][nn] = __float2half_rn(W[((size_t)e * DIM + kb + kk) * ODIM + nb + nn]);
        }
    }
    __syncthreads();
    {
        size_t ob = (size_t)(l * NEXP + e) * ODIM;
        int kk = tid & 63, n0 = tid >> 6;
#pragma unroll
        for (int i = 0; i < 16; ++i) {
            int nn = n0 + i * 4;
            g_w[(ob + nb + nn) * DIM + kb + kk] = sh[kk][nn];
        }
    }
}

// ---------------- activation convert (layer0, gathered) ----------------
__global__ void convert_a_kernel(const float* __restrict__ x) {
    int r = blockIdx.x;
    int tok = g_row_token[r];
    int c = threadIdx.x;
    float4 v = make_float4(0.f, 0.f, 0.f, 0.f);
    if (tok >= 0) v = *(const float4*)(x + (size_t)tok * DIM + c * 4);
    *(uint2*)(&g_a[0][(size_t)r * DIM + c * 4]) =
        make_uint2(pack_h2(__float2half_rn(v.x), __float2half_rn(v.y)),
                   pack_h2(__float2half_rn(v.z), __float2half_rn(v.w)));
}

// ---------------- HMMA grouped GEMM (single-pass fp16, fp32 accum) ----------------
// LAYER 0: A = g_a[0] -> g_a[1]; LAYER 1: g_a[1] -> g_a[0]; LAYER 2: g_a[0] -> g_y
#define OFF_A  0
#define OFF_B  8192
#define STAGE_BYTES 16384
#define NSTAGE 4
#define SMEM_NEED (NSTAGE * STAGE_BYTES + 128)

template <int LAYER>
__global__ void __launch_bounds__(256, 2)
moe_gemm_mma(const float* __restrict__ Bias) {
    const __half* Ain = g_a[(LAYER == 1) ? 1 : 0];
    __half* Oa = (LAYER == 0) ? g_a[1] : g_a[0];

    int total = g_offsets[NEXP];
    int mbase = blockIdx.y * BM;
    if (mbase >= total) return;
    int e = 0;
    while (e < NEXP - 1 && mbase >= g_offsets[e + 1]) e++;
    int nbase = blockIdx.x * BN;

    extern __shared__ char smraw[];
    u32 sraw = smem_u32(smraw);
    u32 sbase = (sraw + 127u) & ~127u;

    int tid = threadIdx.x;
    int wid = tid >> 5, lid = tid & 31;
    int wm = wid & 3, wn = wid >> 2;

    const __half* Wp = g_w + ((size_t)(LAYER * NEXP + e) * ODIM + nbase) * DIM;
    const __half* Ap = Ain + (size_t)mbase * DIM;

    // per-thread cp.async indices: 512 16B-chunks per region, 2 per thread
    int r0 = tid >> 2, c0 = tid & 3;
    int r1 = (tid + 256) >> 2, c1 = tid & 3;
    u32 d0 = swz_off(r0, c0), d1 = swz_off(r1, c1);
    size_t s0 = (size_t)r0 * DIM + c0 * 8;
    size_t s1 = (size_t)r1 * DIM + c1 * 8;

    float acc[2][8][4];
#pragma unroll
    for (int i = 0; i < 2; ++i)
#pragma unroll
        for (int j = 0; j < 8; ++j)
#pragma unroll
            for (int q = 0; q < 4; ++q) acc[i][j][q] = 0.f;

#define PREFETCH(ch) do {                                                      \
    u32 sb = sbase + ((ch) % NSTAGE) * STAGE_BYTES;                            \
    int kk = (ch) * BK;                                                        \
    cp16(sb + OFF_A + d0, Ap + s0 + kk);                                       \
    cp16(sb + OFF_A + d1, Ap + s1 + kk);                                       \
    cp16(sb + OFF_B + d0, Wp + s0 + kk);                                       \
    cp16(sb + OFF_B + d1, Wp + s1 + kk);                                       \
    cp_commit();                                                               \
} while (0)

    PREFETCH(0);
    PREFETCH(1);
    PREFETCH(2);

    for (int ch = 0; ch < NCH; ++ch) {
        if (ch + 3 < NCH) { PREFETCH(ch + 3); cp_wait<3>(); }
        else if (ch + 2 < NCH) { cp_wait<2>(); }
        else if (ch + 1 < NCH) { cp_wait<1>(); }
        else { cp_wait<0>(); }
        __syncthreads();

        u32 sb = sbase + (ch % NSTAGE) * STAGE_BYTES;
#pragma unroll
        for (int s = 0; s < 2; ++s) {
            u32 af[2][4];
#pragma unroll
            for (int mt = 0; mt < 2; ++mt) {
                int r = wm * 32 + mt * 16 + (lid & 15);
                int chunk = s * 2 + (lid >> 4);
                LDM_X4(af[mt], sb + OFF_A + swz_off(r, chunk));
            }
#pragma unroll
            for (int p = 0; p < 4; ++p) {
                int n = wn * 64 + p * 16 + ((lid >> 4) << 3) + (lid & 7);
                int chunk = s * 2 + ((lid >> 3) & 1);
                u32 bh[4];
                LDM_X4(bh, sb + OFF_B + swz_off(n, chunk));
#pragma unroll
                for (int mt = 0; mt < 2; ++mt) {
                    MMA16816(acc[mt][2 * p + 0], af[mt], bh[0], bh[1]);
                    MMA16816(acc[mt][2 * p + 1], af[mt], bh[2], bh[3]);
                }
            }
        }
        __syncthreads();
    }
#undef PREFETCH

    // epilogue: bias + relu, write next layer fp16 (or fp32 y)
#pragma unroll
    for (int mt = 0; mt < 2; ++mt) {
#pragma unroll
        for (int nt = 0; nt < 8; ++nt) {
            int row = mbase + wm * 32 + mt * 16 + (lid >> 2);
            int n0 = nbase + wn * 64 + nt * 8 + (lid & 3) * 2;
            float bb0 = __ldg(Bias + e * ODIM + n0);
            float bb1 = __ldg(Bias + e * ODIM + n0 + 1);
            float v00 = fmaxf(acc[mt][nt][0] + bb0, 0.f);
            float v01 = fmaxf(acc[mt][nt][1] + bb1, 0.f);
            float v10 = fmaxf(acc[mt][nt][2] + bb0, 0.f);
            float v11 = fmaxf(acc[mt][nt][3] + bb1, 0.f);
            if (LAYER < 2) {
                *(u32*)(Oa + (size_t)row * DIM + n0) =
                    pack_h2(__float2half_rn(v00), __float2half_rn(v01));
                *(u32*)(Oa + (size_t)(row + 8) * DIM + n0) =
                    pack_h2(__float2half_rn(v10), __float2half_rn(v11));
            } else {
                *(float2*)(g_y + (size_t)row * ODIM + n0)       = make_float2(v00, v01);
                *(float2*)(g_y + (size_t)(row + 8) * ODIM + n0) = make_float2(v10, v11);
            }
        }
    }
}

// ---------------- combine ----------------
__global__ void combine_kernel(float* __restrict__ out) {
    int tok = blockIdx.x;
    int r0 = g_tok_rows[tok * 2 + 0];
    int r1 = g_tok_rows[tok * 2 + 1];
    float w0 = g_tok_w[tok * 2 + 0];
    float w1 = g_tok_w[tok * 2 + 1];
    const float4* y0 = (const float4*)(g_y + (size_t)r0 * ODIM);
    const float4* y1 = (const float4*)(g_y + (size_t)r1 * ODIM);
    float4* o = (float4*)(out + (size_t)tok * ODIM);
    for (int c = threadIdx.x; c < ODIM / 4; c += blockDim.x) {
        float4 a = y0[c], b = y1[c];
        o[c] = make_float4(w0 * a.x + w1 * b.x, w0 * a.y + w1 * b.y,
                           w0 * a.z + w1 * b.z, w0 * a.w + w1 * b.w);
    }
}

// ---------------- launch ----------------
extern "C" void kernel_launch(void* const* d_in, const int* in_sizes, int n_in,
                              void* d_out, int out_size) {
    const float* x  = (const float*)d_in[0];
    const float* gw = (const float*)d_in[1];
    const float* gb = (const float*)d_in[2];
    const float* w1 = (const float*)d_in[3];
    const float* b1 = (const float*)d_in[4];
    const float* w2 = (const float*)d_in[5];
    const float* b2 = (const float*)d_in[6];
    const float* w3 = (const float*)d_in[7];
    const float* b3 = (const float*)d_in[8];
    float* out = (float*)d_out;

    cudaFuncSetAttribute(moe_gemm_mma<0>, cudaFuncAttributeMaxDynamicSharedMemorySize, SMEM_NEED);
    cudaFuncSetAttribute(moe_gemm_mma<1>, cudaFuncAttributeMaxDynamicSharedMemorySize, SMEM_NEED);
    cudaFuncSetAttribute(moe_gemm_mma<2>, cudaFuncAttributeMaxDynamicSharedMemorySize, SMEM_NEED);

    init_kernel<<<(MAXROWS + 255) / 256, 256>>>();
    gate_kernel<<<N_TOK / 8, 256>>>(x, gw, gb);
    route_kernel<<<1, 256>>>();
    convert_w_kernel<<<dim3(64, NEXP, 3), 256>>>(w1, w2, w3);
    convert_a_kernel<<<MAXROWS, 128>>>(x);

    dim3 grid(NTILES, MTILES);
    moe_gemm_mma<0><<<grid, 256, SMEM_NEED>>>(b1);
    moe_gemm_mma<1><<<grid, 256, SMEM_NEED>>>(b2);
    moe_gemm_mma<2><<<grid, 256, SMEM_NEED>>>(b3);

    combine_kernel<<<N_TOK, 128>>>(out);
}

// round 16
// speedup vs baseline: 4.0808x; 1.0832x over previous
#include <cuda_runtime.h>
#include <cuda_fp16.h>
#include <stdint.h>

// ---------------- problem constants ----------------
#define N_TOK 4096
#define DIM   512
#define ODIM  512
#define NEXP  8
#define TOPK  2

// ---------------- GEMM tiling ----------------
#define BM 128
#define BN 128
#define BK 32
#define NCH (DIM / BK)                      // 16 k-chunks
#define MAXROWS (N_TOK * TOPK + NEXP * BM)  // 9216
#define MTILES  (MAXROWS / BM)              // 72
#define NTILES  (ODIM / BN)                 // 4

typedef unsigned int u32;
typedef unsigned long long u64;

// ---------------- device scratch ----------------
__device__ int   g_counts[NEXP];
__device__ int   g_offsets[NEXP + 1];
__device__ int   g_row_token[MAXROWS];
__device__ int   g_top_e[N_TOK * TOPK];
__device__ int   g_tok_rows[N_TOK * TOPK];
__device__ float g_tok_w[N_TOK * TOPK];
__device__ float g_y[(size_t)MAXROWS * ODIM];
// weights, fp16, ORIGINAL [layer][e][k][n] layout (no transpose)
__device__ __half g_w[(size_t)3 * NEXP * DIM * ODIM];
// activations: token-order fp16 (layer-0 input), row-order ping-pong
__device__ __half g_ax[(size_t)N_TOK * DIM];
__device__ __half g_a[2][(size_t)MAXROWS * DIM];

// ---------------- PTX helpers ----------------
__device__ __forceinline__ u32 smem_u32(const void* p) {
    u32 a;
    asm("{ .reg .u64 t; cvta.to.shared.u64 t, %1; cvt.u32.u64 %0, t; }" : "=r"(a) : "l"(p));
    return a;
}
__device__ __forceinline__ void cp16(u32 dst, const void* src) {
    asm volatile("cp.async.cg.shared.global [%0], [%1], 16;" :: "r"(dst), "l"(src) : "memory");
}
__device__ __forceinline__ void cp_commit() {
    asm volatile("cp.async.commit_group;" ::: "memory");
}
template <int N>
__device__ __forceinline__ void cp_wait() {
    asm volatile("cp.async.wait_group %0;" :: "n"(N) : "memory");
}
#define LDM_X4(d, addr)                                                        \
    asm volatile("ldmatrix.sync.aligned.m8n8.x4.shared.b16 {%0,%1,%2,%3}, [%4];" \
        : "=r"((d)[0]), "=r"((d)[1]), "=r"((d)[2]), "=r"((d)[3]) : "r"(addr))
#define LDM_X4T(d, addr)                                                       \
    asm volatile("ldmatrix.sync.aligned.m8n8.x4.trans.shared.b16 {%0,%1,%2,%3}, [%4];" \
        : "=r"((d)[0]), "=r"((d)[1]), "=r"((d)[2]), "=r"((d)[3]) : "r"(addr))
#define MMA16816(c, a, bv0, bv1)                                               \
    asm volatile("mma.sync.aligned.m16n8k16.row.col.f32.f16.f16.f32 "          \
        "{%0,%1,%2,%3}, {%4,%5,%6,%7}, {%8,%9}, {%0,%1,%2,%3};"                \
        : "+f"((c)[0]), "+f"((c)[1]), "+f"((c)[2]), "+f"((c)[3])               \
        : "r"((a)[0]), "r"((a)[1]), "r"((a)[2]), "r"((a)[3]), "r"(bv0), "r"(bv1))

__device__ __forceinline__ u32 pack_h2(__half a, __half b) {
    return (u32)__half_as_ushort(a) | ((u32)__half_as_ushort(b) << 16);
}
// A tile swizzle: [128 rows][32 k] fp16, row=64B, 4 chunks of 16B
__device__ __forceinline__ u32 swz_off(int r, int c) {
    return (u32)(r * 64 + ((c ^ ((r >> 1) & 3)) << 4));
}
// B tile swizzle: [32 k rows][128 n] fp16, row=256B, 16 chunks of 16B
__device__ __forceinline__ u32 bswz(int r, int c) {
    return (u32)(r * 256 + (((c) ^ (r & 7)) << 4));
}

// ---------------- activation convert (token order) + counts init ----------------
__global__ void convert_a_kernel(const float* __restrict__ x) {
    if (blockIdx.x == 0 && threadIdx.x < NEXP) g_counts[threadIdx.x] = 0;
    int tok = blockIdx.x;
    int c = threadIdx.x;  // 128 threads, 4 floats each
    float4 v = *(const float4*)(x + (size_t)tok * DIM + c * 4);
    *(uint2*)(&g_ax[(size_t)tok * DIM + c * 4]) =
        make_uint2(pack_h2(__float2half_rn(v.x), __float2half_rn(v.y)),
                   pack_h2(__float2half_rn(v.z), __float2half_rn(v.w)));
}

// ---------------- weight convert: pure streaming fp32 -> fp16 ----------------
__global__ void convert_w_kernel(const float* __restrict__ w1,
                                 const float* __restrict__ w2,
                                 const float* __restrict__ w3) {
    const size_t PER_L = (size_t)NEXP * DIM * ODIM / 4;   // float4s per layer
    const size_t TOTAL = 3 * PER_L;
    size_t stride = (size_t)gridDim.x * blockDim.x;
#pragma unroll 1
    for (size_t i = (size_t)blockIdx.x * blockDim.x + threadIdx.x; i < TOTAL; i += stride) {
        int l = (int)(i / PER_L);
        size_t j = i - (size_t)l * PER_L;
        const float* W = (l == 0) ? w1 : (l == 1) ? w2 : w3;
        float4 v = ((const float4*)W)[j];
        ((uint2*)g_w)[i] =
            make_uint2(pack_h2(__float2half_rn(v.x), __float2half_rn(v.y)),
                       pack_h2(__float2half_rn(v.z), __float2half_rn(v.w)));
    }
}

// ---------------- gating: one warp per token ----------------
__global__ void gate_kernel(const float* __restrict__ x,
                            const float* __restrict__ gw,
                            const float* __restrict__ gb) {
    int warp = (blockIdx.x * blockDim.x + threadIdx.x) >> 5;
    int lane = threadIdx.x & 31;
    if (warp >= N_TOK) return;
    const float* xr = x + (size_t)warp * DIM;

    float acc[NEXP];
#pragma unroll
    for (int e = 0; e < NEXP; ++e) acc[e] = 0.f;
    for (int i = lane; i < DIM; i += 32) {
        float xv = xr[i];
        const float4* g4 = (const float4*)(gw + (size_t)i * NEXP);
        float4 a = g4[0], b = g4[1];
        acc[0] += xv * a.x; acc[1] += xv * a.y; acc[2] += xv * a.z; acc[3] += xv * a.w;
        acc[4] += xv * b.x; acc[5] += xv * b.y; acc[6] += xv * b.z; acc[7] += xv * b.w;
    }
#pragma unroll
    for (int e = 0; e < NEXP; ++e)
#pragma unroll
        for (int off = 16; off; off >>= 1)
            acc[e] += __shfl_xor_sync(0xffffffffu, acc[e], off);

    if (lane == 0) {
        float lg[NEXP], mx = -1e30f;
#pragma unroll
        for (int e = 0; e < NEXP; ++e) { lg[e] = acc[e] + gb[e]; mx = fmaxf(mx, lg[e]); }
        float p[NEXP], s = 0.f;
#pragma unroll
        for (int e = 0; e < NEXP; ++e) { p[e] = expf(lg[e] - mx); s += p[e]; }
        float inv = 1.0f / s;
        int i0 = 0;
#pragma unroll
        for (int e = 1; e < NEXP; ++e) if (lg[e] > lg[i0]) i0 = e;
        int i1 = -1;
#pragma unroll
        for (int e = 0; e < NEXP; ++e)
            if (e != i0 && (i1 < 0 || lg[e] > lg[i1])) i1 = e;
        // Faithful quirk: slot j combine weight is probs[n, j]
        g_top_e[warp * 2 + 0] = i0;
        g_top_e[warp * 2 + 1] = i1;
        g_tok_w[warp * 2 + 0] = p[0] * inv;
        g_tok_w[warp * 2 + 1] = p[1] * inv;
        atomicAdd(&g_counts[i0], 1);
        atomicAdd(&g_counts[i1], 1);
    }
}

// ---------------- route: offsets (padded to BM) + row_token init + scatter ----------------
__global__ void route_kernel() {
    __shared__ int soff[NEXP];
    __shared__ int scur[NEXP];
    int tid = threadIdx.x;
    if (tid == 0) {
        int off = 0;
#pragma unroll
        for (int e = 0; e < NEXP; ++e) {
            g_offsets[e] = off;
            soff[e] = off;
            off += ((g_counts[e] + BM - 1) / BM) * BM;
        }
        g_offsets[NEXP] = off;
    }
    if (tid < NEXP) scur[tid] = 0;
    for (int i = tid; i < MAXROWS; i += blockDim.x) g_row_token[i] = -1;
    __syncthreads();
    for (int i = tid; i < N_TOK * TOPK; i += blockDim.x) {
        int e = g_top_e[i];
        int pos = atomicAdd(&scur[e], 1);
        int r = soff[e] + pos;
        g_row_token[r] = i >> 1;
        g_tok_rows[i] = r;
    }
}

// ---------------- HMMA grouped GEMM (single-pass fp16, fp32 accum) ----------------
// LAYER 0: A = g_ax (gathered via g_row_token) -> g_a[1]
// LAYER 1: A = g_a[1] -> g_a[0]
// LAYER 2: A = g_a[0] -> g_y (fp32)
#define OFF_A  0
#define OFF_B  8192
#define STAGE_BYTES 16384
#define NSTAGE 4
#define SMEM_NEED (NSTAGE * STAGE_BYTES + 128)

template <int LAYER>
__global__ void __launch_bounds__(256, 2)
moe_gemm_mma(const float* __restrict__ Bias) {
    constexpr bool GATHER = (LAYER == 0);
    const __half* Ain = (LAYER == 1) ? g_a[1] : g_a[0];  // unused for LAYER 0
    __half* Oa = (LAYER == 0) ? g_a[1] : g_a[0];

    int total = g_offsets[NEXP];
    int mbase = blockIdx.y * BM;
    if (mbase >= total) return;
    int e = 0;
    while (e < NEXP - 1 && mbase >= g_offsets[e + 1]) e++;
    int nbase = blockIdx.x * BN;

    extern __shared__ char smraw[];
    u32 sraw = smem_u32(smraw);
    u32 sbase = (sraw + 127u) & ~127u;
    __shared__ int rtok[BM];

    int tid = threadIdx.x;
    int wid = tid >> 5, lid = tid & 31;
    int wm = wid & 3, wn = wid >> 2;

    if (GATHER) {
        if (tid < BM) {
            int t = g_row_token[mbase + tid];
            rtok[tid] = (t < 0) ? 0 : t;
        }
        __syncthreads();
    }

    // weights in [k][n]: row k has ODIM halves
    const __half* Wp = g_w + (size_t)(LAYER * NEXP + e) * DIM * ODIM;

    // A cp.async: 512 chunks = 128 rows x 4 chunks; 2 per thread
    int ar0 = tid >> 2, ac0 = tid & 3;
    int ar1 = ar0 + 64;
    u32 da0 = swz_off(ar0, ac0), da1 = swz_off(ar1, ac0);
    const __half* asrc0;
    const __half* asrc1;
    if (GATHER) {
        asrc0 = g_ax + (size_t)rtok[ar0] * DIM + ac0 * 8;
        asrc1 = g_ax + (size_t)rtok[ar1] * DIM + ac0 * 8;
    } else {
        asrc0 = Ain + (size_t)(mbase + ar0) * DIM + ac0 * 8;
        asrc1 = Ain + (size_t)(mbase + ar1) * DIM + ac0 * 8;
    }

    // B cp.async: 512 chunks = 32 k-rows x 16 chunks; 2 per thread
    int br0 = tid >> 4, bc = tid & 15;
    int br1 = br0 + 16;
    u32 db0 = bswz(br0, bc), db1 = bswz(br1, bc);
    const __half* bsrc0 = Wp + (size_t)br0 * ODIM + nbase + bc * 8;
    const __half* bsrc1 = Wp + (size_t)br1 * ODIM + nbase + bc * 8;

    float acc[2][8][4];
#pragma unroll
    for (int i = 0; i < 2; ++i)
#pragma unroll
        for (int j = 0; j < 8; ++j)
#pragma unroll
            for (int q = 0; q < 4; ++q) acc[i][j][q] = 0.f;

#define PREFETCH(ch) do {                                                      \
    u32 sb = sbase + ((ch) % NSTAGE) * STAGE_BYTES;                            \
    int kk = (ch) * BK;                                                        \
    cp16(sb + OFF_A + da0, asrc0 + kk);                                        \
    cp16(sb + OFF_A + da1, asrc1 + kk);                                        \
    cp16(sb + OFF_B + db0, bsrc0 + (size_t)kk * ODIM);                         \
    cp16(sb + OFF_B + db1, bsrc1 + (size_t)kk * ODIM);                         \
    cp_commit();                                                               \
} while (0)

    PREFETCH(0);
    PREFETCH(1);
    PREFETCH(2);

    for (int ch = 0; ch < NCH; ++ch) {
        if (ch < NCH - 2)       cp_wait<2>();
        else if (ch == NCH - 2) cp_wait<1>();
        else                    cp_wait<0>();
        __syncthreads();
        if (ch + 3 < NCH) PREFETCH(ch + 3);

        u32 sb = sbase + (ch % NSTAGE) * STAGE_BYTES;
#pragma unroll
        for (int s = 0; s < 2; ++s) {
            u32 af[2][4];
#pragma unroll
            for (int mt = 0; mt < 2; ++mt) {
                int r = wm * 32 + mt * 16 + (lid & 15);
                int chunk = s * 2 + (lid >> 4);
                LDM_X4(af[mt], sb + OFF_A + swz_off(r, chunk));
            }
            int grp = lid >> 3, rr = lid & 7;
            int krow = s * 16 + ((grp & 1) << 3) + rr;
#pragma unroll
            for (int p = 0; p < 4; ++p) {
                int nch = ((wn * 64 + p * 16) >> 3) + (grp >> 1);
                u32 bh[4];
                LDM_X4T(bh, sb + OFF_B + bswz(krow, nch));
#pragma unroll
                for (int mt = 0; mt < 2; ++mt) {
                    MMA16816(acc[mt][2 * p + 0], af[mt], bh[0], bh[1]);
                    MMA16816(acc[mt][2 * p + 1], af[mt], bh[2], bh[3]);
                }
            }
        }
    }
#undef PREFETCH

    // epilogue: bias + relu, write next layer fp16 (or fp32 y)
#pragma unroll
    for (int mt = 0; mt < 2; ++mt) {
#pragma unroll
        for (int nt = 0; nt < 8; ++nt) {
            int row = mbase + wm * 32 + mt * 16 + (lid >> 2);
            int n0 = nbase + wn * 64 + nt * 8 + (lid & 3) * 2;
            float bb0 = __ldg(Bias + e * ODIM + n0);
            float bb1 = __ldg(Bias + e * ODIM + n0 + 1);
            float v00 = fmaxf(acc[mt][nt][0] + bb0, 0.f);
            float v01 = fmaxf(acc[mt][nt][1] + bb1, 0.f);
            float v10 = fmaxf(acc[mt][nt][2] + bb0, 0.f);
            float v11 = fmaxf(acc[mt][nt][3] + bb1, 0.f);
            if (LAYER < 2) {
                *(u32*)(Oa + (size_t)row * DIM + n0) =
                    pack_h2(__float2half_rn(v00), __float2half_rn(v01));
                *(u32*)(Oa + (size_t)(row + 8) * DIM + n0) =
                    pack_h2(__float2half_rn(v10), __float2half_rn(v11));
            } else {
                *(float2*)(g_y + (size_t)row * ODIM + n0)       = make_float2(v00, v01);
                *(float2*)(g_y + (size_t)(row + 8) * ODIM + n0) = make_float2(v10, v11);
            }
        }
    }
}

// ---------------- combine ----------------
__global__ void combine_kernel(float* __restrict__ out) {
    int tok = blockIdx.x;
    int r0 = g_tok_rows[tok * 2 + 0];
    int r1 = g_tok_rows[tok * 2 + 1];
    float w0 = g_tok_w[tok * 2 + 0];
    float w1 = g_tok_w[tok * 2 + 1];
    const float4* y0 = (const float4*)(g_y + (size_t)r0 * ODIM);
    const float4* y1 = (const float4*)(g_y + (size_t)r1 * ODIM);
    float4* o = (float4*)(out + (size_t)tok * ODIM);
    for (int c = threadIdx.x; c < ODIM / 4; c += blockDim.x) {
        float4 a = y0[c], b = y1[c];
        o[c] = make_float4(w0 * a.x + w1 * b.x, w0 * a.y + w1 * b.y,
                           w0 * a.z + w1 * b.z, w0 * a.w + w1 * b.w);
    }
}

// ---------------- launch ----------------
extern "C" void kernel_launch(void* const* d_in, const int* in_sizes, int n_in,
                              void* d_out, int out_size) {
    const float* x  = (const float*)d_in[0];
    const float* gw = (const float*)d_in[1];
    const float* gb = (const float*)d_in[2];
    const float* w1 = (const float*)d_in[3];
    const float* b1 = (const float*)d_in[4];
    const float* w2 = (const float*)d_in[5];
    const float* b2 = (const float*)d_in[6];
    const float* w3 = (const float*)d_in[7];
    const float* b3 = (const float*)d_in[8];
    float* out = (float*)d_out;

    cudaFuncSetAttribute(moe_gemm_mma<0>, cudaFuncAttributeMaxDynamicSharedMemorySize, SMEM_NEED);
    cudaFuncSetAttribute(moe_gemm_mma<1>, cudaFuncAttributeMaxDynamicSharedMemorySize, SMEM_NEED);
    cudaFuncSetAttribute(moe_gemm_mma<2>, cudaFuncAttributeMaxDynamicSharedMemorySize, SMEM_NEED);

    convert_a_kernel<<<N_TOK, 128>>>(x);          // also zeroes g_counts (block 0)
    convert_w_kernel<<<1536, 256>>>(w1, w2, w3);
    gate_kernel<<<N_TOK / 8, 256>>>(x, gw, gb);
    route_kernel<<<1, 512>>>();

    dim3 grid(NTILES, MTILES);
    moe_gemm_mma<0><<<grid, 256, SMEM_NEED>>>(b1);
    moe_gemm_mma<1><<<grid, 256, SMEM_NEED>>>(b2);
    moe_gemm_mma<2><<<grid, 256, SMEM_NEED>>>(b3);

    combine_kernel<<<N_TOK, 128>>>(out);
}